// round 13
// baseline (speedup 1.0000x reference)
#include <cuda_runtime.h>
#include <cuda_fp16.h>
#include <math.h>
#include <stdint.h>

#define Tn 64
#define Bn 64
#define Sn 512
#define An 16
#define Rn 64
#define Hn 32
#define EPSF 1e-6f
#define BSCALE 4096.f

#define NUNITS 128       // persistent CTAs: one per 4-j chunk (all 16 k local)

// dynamic smem layout (bytes)
#define TSL_B    65536           // T slab: [32 ib][8 col8][32 lane][2 reg] fp16 = 64 KB
#define CSH_ROW4 65              // uint4 per belief row (512 halves + 8 pad)
#define CSH_B    (64*CSH_ROW4*16)    // 66560
#define AWSH_F   (64*17)
#define SMEM_TOT (TSL_B + CSH_B + AWSH_F*4 + 256*4 + 64*4)   // 137728

// ---------------- scratch (device globals; no allocation) ----------------
// T permuted: [jc(128)][ib(32)][col8(8)][lane(32)][reg(2)] halves, col = k*4 + (j&3)
__device__ __align__(16) unsigned short g_transPh[(size_t)An*Sn*Sn];  // 8.4 MB
__device__ float g_G[Sn*Sn];
__device__ float g_p[An*Sn];
__device__ float g_taupdf[Hn];
__device__ float g_alpha_a[(size_t)Tn*Bn*An];
__device__ __align__(16) __half g_belN[2*Bn*Sn];              // double-buffered belief [n][i], scaled x4096
__device__ __align__(16) float g_po[(size_t)Tn*Bn*Sn];        // exp(logp_o), 8 MB
__device__ __align__(16) float g_normP[(Tn+1)*Bn*8];          // per (t+1, n, slot) norm partials

// decentralized barrier: one monotonic flag per CTA (uniform at launch boundaries)
__device__ __align__(128) unsigned g_flags[NUNITS];

// ---------------- helpers ----------------
__device__ __forceinline__ uint32_t f2tf32(float x) {
    uint32_t u;
    asm("cvt.rna.tf32.f32 %0, %1;" : "=r"(u) : "f"(x));
    return u;
}

__device__ __forceinline__ void red_add(float* p, float v) {
    asm volatile("red.global.add.f32 [%0], %1;" :: "l"(p), "f"(v) : "memory");
}

__device__ __forceinline__ unsigned ldv(const unsigned* p) {
    unsigned v;
    asm volatile("ld.volatile.global.u32 %0, [%1];" : "=r"(v) : "l"(p));
    return v;
}
__device__ __forceinline__ void stv(unsigned* p, unsigned v) {
    asm volatile("st.volatile.global.u32 [%0], %1;" :: "l"(p), "r"(v) : "memory");
}

__device__ __forceinline__ void mma_f16(float& c0, float& c1, float& c2, float& c3,
                                        uint32_t a0, uint32_t a1, uint32_t a2, uint32_t a3,
                                        uint32_t b0, uint32_t b1) {
    asm volatile("mma.sync.aligned.m16n8k16.row.col.f32.f16.f16.f32 "
                 "{%0,%1,%2,%3},{%4,%5,%6,%7},{%8,%9},{%0,%1,%2,%3};\n"
                 : "+f"(c0), "+f"(c1), "+f"(c2), "+f"(c3)
                 : "r"(a0), "r"(a1), "r"(a2), "r"(a3), "r"(b0), "r"(b1));
}

__device__ __forceinline__ void mma_tf32(float& c0, float& c1, float& c2, float& c3,
                                         uint32_t a0, uint32_t a1, uint32_t a2, uint32_t a3,
                                         uint32_t b0, uint32_t b1) {
    asm volatile("mma.sync.aligned.m16n8k8.row.col.f32.tf32.tf32.f32 "
                 "{%0,%1,%2,%3},{%4,%5,%6,%7},{%8,%9},{%0,%1,%2,%3};\n"
                 : "+f"(c0), "+f"(c1), "+f"(c2), "+f"(c3)
                 : "r"(a0), "r"(a1), "r"(a2), "r"(a3), "r"(b0), "r"(b1));
}

// ---------------- precompute: v_norm and p[k][i] = u[i].v_hat[k] ----------------
__global__ void k_pv(const float* __restrict__ u, const float* __restrict__ v) {
    int k = blockIdx.x;
    int t = threadIdx.x;  // 64
    __shared__ float vn[Rn];
    __shared__ float sb[64];
    float x = v[k*Rn + t];
    sb[t] = x * x;
    __syncthreads();
    for (int s = 32; s > 0; s >>= 1) { if (t < s) sb[t] += sb[t+s]; __syncthreads(); }
    vn[t] = x * rsqrtf(sb[0]);
    __syncthreads();
    for (int i = t; i < Sn; i += 64) {
        float s = 0.f;
        #pragma unroll
        for (int r = 0; r < Rn; r++) s += u[i*Rn + r] * vn[r];
        g_p[k*Sn + i] = s;
    }
}

// ---------------- precompute: G[i][j] = u[i].u[j] ----------------
__global__ void k_gram(const float* __restrict__ u) {
    int i = blockIdx.x;
    int tid = threadIdx.x;  // 128
    __shared__ float ui[Rn];
    if (tid < Rn) ui[tid] = u[i*Rn + tid];
    __syncthreads();
    for (int j = tid; j < Sn; j += 128) {
        float s = 0.f;
        #pragma unroll
        for (int r = 0; r < Rn; r++) s += u[j*Rn + r] * ui[r];
        g_G[i*Sn + j] = s;
    }
}

// ---------------- precompute: transition softmax -> j-chunk-sliced fp16 fragment layout ----------------
// block (ib, k): 16 warps, one per row r; each lane owns 16 j-values (j = lane + 32q).
// element (k,i,j) -> slab jc=j>>2, col = k*4 + (j&3):
//   stage[jc*64 + jj*16 + ((r&7)>>1)*4 + (r>>3)*2 + (r&1)]
__global__ void __launch_bounds__(512) k_trans16() {
    int ib = blockIdx.x, k = blockIdx.y;   // ib 0..31, k 0..15
    int tid = threadIdx.x;                 // 512
    int r = tid >> 5;                      // warp = row 0..15
    int lane = tid & 31;
    __shared__ __align__(16) unsigned short stage[8192];

    int i = ib*16 + r;
    float pki2 = 2.f * g_p[k*Sn + i];
    const float* Grow = &g_G[i*Sn];
    const float* prow = &g_p[k*Sn];

    float w[16];
    float m = -1e30f;
    #pragma unroll
    for (int q = 0; q < 16; q++) {
        int j = lane + 32*q;
        w[q] = Grow[j] - pki2 * prow[j];
        m = fmaxf(m, w[q]);
    }
    #pragma unroll
    for (int o = 16; o > 0; o >>= 1) m = fmaxf(m, __shfl_xor_sync(0xffffffffu, m, o));
    float s = 0.f;
    #pragma unroll
    for (int q = 0; q < 16; q++) { w[q] = expf(w[q] - m); s += w[q]; }
    #pragma unroll
    for (int o = 16; o > 0; o >>= 1) s += __shfl_xor_sync(0xffffffffu, s, o);
    float inv = 1.f / s;
    int rbits = ((r & 7) >> 1)*4 + (r >> 3)*2 + (r & 1);
    #pragma unroll
    for (int q = 0; q < 16; q++) {
        int j = lane + 32*q;
        stage[(j >> 2)*64 + (j & 3)*16 + rbits] =
            __half_as_ushort(__float2half_rn(w[q] * inv));
    }
    __syncthreads();

    // coalesced writeout: 1024 uint4
    const uint4* s4 = reinterpret_cast<const uint4*>(stage);
    uint4* d4 = reinterpret_cast<uint4*>(g_transPh);
    #pragma unroll
    for (int q = 0; q < 2; q++) {
        int f = tid + q*512;               // 0..1023
        int jc2 = f >> 3, o = f & 7;
        size_t idx4 = ((size_t)(jc2*32 + ib)*8 + (k >> 1))*16 + (k & 1)*8 + o;
        d4[idx4] = s4[f];
    }
}

// ---------------- precompute: normalized Poisson pdf over horizon ----------------
__global__ void k_taupdf(const float* __restrict__ tau) {
    int t = threadIdx.x;  // 32
    float rate = log1pf(expf(tau[0]));
    float kk = (float)(t + 1);
    float lp = kk * logf(rate) - rate - lgammaf(kk + 1.f);
    float p = expf(lp);
    float s = p;
    #pragma unroll
    for (int o = 16; o > 0; o >>= 1) s += __shfl_xor_sync(0xffffffffu, s, o);
    g_taupdf[t] = p / s;
}

// ---------------- precompute: alpha_a = softmax(logp_u) over A ----------------
__global__ void k_alpha_a(const float* __restrict__ logp_u) {
    int idx = blockIdx.x * blockDim.x + threadIdx.x;
    if (idx >= Tn*Bn) return;
    const float* r = logp_u + (size_t)idx*An;
    float m = -1e30f;
    #pragma unroll
    for (int k = 0; k < An; k++) m = fmaxf(m, r[k]);
    float e[An]; float s = 0.f;
    #pragma unroll
    for (int k = 0; k < An; k++) { e[k] = expf(r[k] - m); s += e[k]; }
    float inv = 1.f / s;
    #pragma unroll
    for (int k = 0; k < An; k++) g_alpha_a[(size_t)idx*An + k] = e[k] * inv;
}

// ---------------- precompute: po = exp(logp_o); also zero the norm partials ----------------
__global__ void k_po(const float* __restrict__ logp_o) {
    size_t idx = (size_t)blockIdx.x * 512 + threadIdx.x;
    g_po[idx] = expf(logp_o[idx]);
    if (idx < (size_t)(Tn+1)*Bn*8) g_normP[idx] = 0.f;
}

// ---------------- init belief: fp16 rows [n][i], scaled; seed norm for t=0 ----------------
__global__ void k_init_bel(const float* __restrict__ b) {
    int n = blockIdx.x, j = threadIdx.x;  // (Bn, Sn)
    __shared__ float red[512];
    float bv = b[n*Sn + j] * BSCALE;
    g_belN[n*Sn + j] = __float2half_rn(bv);
    red[j] = bv; __syncthreads();
    for (int s = 256; s > 0; s >>= 1) { if (j < s) red[j] += red[j+s]; __syncthreads(); }
    if (j == 0) g_normP[n*8] = red[0];    // t=0 reads slot sums at index 0
}

// ---------------- fused persistent scan: per-CTA j-chunk, decentralized flag barrier ----------------
__global__ void __launch_bounds__(256, 1)
k_scan(float* __restrict__ out_b) {
    extern __shared__ char smem[];
    uint4*          Tsl4 = reinterpret_cast<uint4*>(smem);
    const uint2*    Tsl2 = reinterpret_cast<const uint2*>(smem);
    char*           cshB = smem + TSL_B;
    uint4*          csh4 = reinterpret_cast<uint4*>(cshB);
    const uint32_t* csh2 = reinterpret_cast<const uint32_t*>(cshB);
    float* awsh  = reinterpret_cast<float*>(cshB + CSH_B);   // [64][17] raw alpha
    float* sacc  = awsh + AWSH_F;                            // [64][4]
    float* invsh = sacc + 256;                               // [64]

    int tid  = threadIdx.x;            // 256
    int jc   = blockIdx.x;             // 0..127 : j-chunk of 4
    int lane = tid & 31;
    int warp = tid >> 5;
    int gid  = lane >> 2;
    int tig  = lane & 3;
    int mw   = warp & 1;               // 2 warps over M (n)
    int nw   = warp >> 1;              // 4 warps over N (cols)
    int nwb  = mw * 32;
    int fn   = tid >> 2;               // final-phase n
    int fj   = tid & 3;                // final-phase jj
    int jj0  = (2*tig) & 3;

    // epoch base: all flags are uniformly equal at every launch boundary
    unsigned fbase = ldv(&g_flags[jc]);

    // one-time: load this CTA's T slab (64 KB, contiguous)
    {
        const uint4* srcT = reinterpret_cast<const uint4*>(g_transPh) + (size_t)jc*4096;
        #pragma unroll
        for (int q = 0; q < 16; q++) Tsl4[tid + q*256] = srcT[tid + q*256];
    }
    __syncthreads();

    for (int t = 0; t < Tn; t++) {
        // prefetch po (off critical path), zero sacc, stage alpha + inv + belief
        float pof = __ldg(&g_po[((size_t)t*Bn + fn)*Sn + jc*4 + fj]);
        sacc[tid] = 0.f;
        #pragma unroll
        for (int q = 0; q < 4; q++) {
            int e = tid + q*256;                         // 0..1023
            awsh[(e >> 4)*17 + (e & 15)] =
                __ldg(&g_alpha_a[((size_t)t*Bn + (e >> 4))*An + (e & 15)]);
        }
        if (tid < Bn) {
            const float4* np = reinterpret_cast<const float4*>(&g_normP[(size_t)t*Bn*8 + tid*8]);
            float4 x = __ldcg(np), y = __ldcg(np + 1);
            invsh[tid] = 1.f / (x.x + x.y + x.z + x.w + y.x + y.y + y.z + y.w);
        }
        {
            const uint4* belc = reinterpret_cast<const uint4*>(g_belN + (size_t)(t & 1)*Bn*Sn);
            #pragma unroll
            for (int q = 0; q < 16; q++) {
                int f = tid + q*256;                     // 0..4095
                csh4[(f >> 6)*CSH_ROW4 + (f & 63)] = __ldcg(&belc[f]);
            }
        }
        __syncthreads();

        // GEMM: M[n, col] = sum_i bel[n,i] * T[i, col], col = k*4+jj (64 cols)
        float c[2][2][4];
        #pragma unroll
        for (int mt = 0; mt < 2; mt++)
            #pragma unroll
            for (int nt = 0; nt < 2; nt++)
                #pragma unroll
                for (int r = 0; r < 4; r++) c[mt][nt][r] = 0.f;

        #pragma unroll 8
        for (int ks = 0; ks < 32; ks++) {
            uint32_t a[2][4];
            #pragma unroll
            for (int mt = 0; mt < 2; mt++) {
                int rb = (nwb + mt*16 + gid)*260 + ks*8 + tig;
                a[mt][0] = csh2[rb];
                a[mt][1] = csh2[rb + 8*260];
                a[mt][2] = csh2[rb + 4];
                a[mt][3] = csh2[rb + 8*260 + 4];
            }
            #pragma unroll
            for (int nt = 0; nt < 2; nt++) {
                uint2 bf = Tsl2[(ks*8 + nw*2 + nt)*32 + lane];
                #pragma unroll
                for (int mt = 0; mt < 2; mt++)
                    mma_f16(c[mt][nt][0], c[mt][nt][1], c[mt][nt][2], c[mt][nt][3],
                            a[mt][0], a[mt][1], a[mt][2], a[mt][3], bf.x, bf.y);
            }
        }

        // epilogue: local k-sum with raw alpha weights -> SMEM atomics
        #pragma unroll
        for (int mt = 0; mt < 2; mt++) {
            int n_a = nwb + mt*16 + gid;
            float pa0 = 0.f, pa1 = 0.f, pb0 = 0.f, pb1 = 0.f;
            #pragma unroll
            for (int nt = 0; nt < 2; nt++) {
                int k = nw*4 + nt*2 + (tig >> 1);
                float wA = awsh[n_a*17 + k];
                float wB = awsh[(n_a + 8)*17 + k];
                pa0 += wA * c[mt][nt][0]; pa1 += wA * c[mt][nt][1];
                pb0 += wB * c[mt][nt][2]; pb1 += wB * c[mt][nt][3];
            }
            atomicAdd(&sacc[n_a*4 + jj0],           pa0);
            atomicAdd(&sacc[n_a*4 + jj0 + 1],       pa1);
            atomicAdd(&sacc[(n_a + 8)*4 + jj0],     pb0);
            atomicAdd(&sacc[(n_a + 8)*4 + jj0 + 1], pb1);
        }
        __syncthreads();

        // finalize: val = (s_norm + eps)*po ; write belief (x4096 fp16), out_b, norm REDs
        {
            float val = (sacc[tid] * invsh[fn] + EPSF) * pof;
            float vs  = val * BSCALE;
            out_b[((size_t)t*Bn + fn)*Sn + jc*4 + fj] = vs;   // unnormalized; fixed post-scan
            unsigned short us = __half_as_ushort(__float2half_rn(vs));
            unsigned short* bp = reinterpret_cast<unsigned short*>(
                g_belN + (size_t)((t + 1) & 1)*Bn*Sn) + fn*Sn + jc*4 + fj;
            asm volatile("st.global.cg.u16 [%0], %1;" :: "l"(bp), "h"(us) : "memory");
            float w = vs;
            w += __shfl_xor_sync(0xffffffffu, w, 1);
            w += __shfl_xor_sync(0xffffffffu, w, 2);
            if ((lane & 3) == 0)
                red_add(&g_normP[(size_t)(t + 1)*Bn*8 + fn*8 + (jc & 7)], w);
        }

        // ---- decentralized grid barrier: own-flag store + parallel poll ----
        __syncthreads();
        __threadfence();
        unsigned target = fbase + (unsigned)(t + 1);
        if (tid == 0) stv(&g_flags[jc], target);
        if (tid < NUNITS) {
            while (ldv(&g_flags[tid]) < target) { }
        }
        __threadfence();
        __syncthreads();
    }
}

// ---------------- post-scan: normalize out_b by per-(t,n) norms ----------------
__global__ void k_fix(float* __restrict__ out_b) {
    int tn = blockIdx.x;            // t*64 + n
    int t = tn >> 6, n = tn & 63;
    __shared__ float inv;
    if (threadIdx.x == 0) {
        const float* np = &g_normP[(size_t)(t + 1)*Bn*8 + n*8];
        float s = np[0] + np[1] + np[2] + np[3] + np[4] + np[5] + np[6] + np[7];
        inv = 1.f / s;
    }
    __syncthreads();
    out_b[(size_t)tn*Sn + threadIdx.x] *= inv;
}

// ---------------- post-scan plan: tf32 MMA logits, softmax over A, tau-weighted sum ----------------
#define HB 4
#define AST 36
__global__ void __launch_bounds__(256)
k_plan(const float* __restrict__ value,
       const float* __restrict__ alpha_b,
       float* __restrict__ out_pi) {
    int n  = blockIdx.x;
    int hq = blockIdx.y;
    int tid = threadIdx.x;
    int lane = tid & 31;
    int warp = tid >> 5;
    int h_l = warp & 3;
    int mh  = warp >> 2;
    int gid = lane >> 2;
    int tig = lane & 3;

    __shared__ uint32_t Ash[64*AST];
    __shared__ uint32_t Vsh[HB*16*AST];
    __shared__ float    Lsh[HB][64][17];

    float c[2][2][4];
    #pragma unroll
    for (int mt = 0; mt < 2; mt++)
        #pragma unroll
        for (int nt = 0; nt < 2; nt++)
            #pragma unroll
            for (int r = 0; r < 4; r++) c[mt][nt][r] = 0.f;

    for (int i0 = 0; i0 < Sn; i0 += 32) {
        #pragma unroll
        for (int q = 0; q < 8; q++) {
            int e = tid + q*256; int ii = e & 31, tt = e >> 5;
            Ash[tt*AST + ii] = f2tf32(alpha_b[((size_t)tt*Bn + n)*Sn + i0 + ii]);
        }
        #pragma unroll
        for (int q = 0; q < 8; q++) {
            int e = tid + q*256; int ii = e & 31, rest = e >> 5;
            int kk2 = rest & 15, hh = rest >> 4;
            Vsh[(hh*16 + kk2)*AST + ii] =
                f2tf32(value[(((size_t)(hq*HB + hh)*Bn + n)*An + kk2)*Sn + i0 + ii]);
        }
        __syncthreads();
        #pragma unroll
        for (int ksl = 0; ksl < 4; ksl++) {
            int ib = ksl*8;
            uint32_t a[2][4];
            #pragma unroll
            for (int mt = 0; mt < 2; mt++) {
                int tr = mh*32 + mt*16;
                a[mt][0] = Ash[(tr + gid    )*AST + ib + tig    ];
                a[mt][1] = Ash[(tr + gid + 8)*AST + ib + tig    ];
                a[mt][2] = Ash[(tr + gid    )*AST + ib + tig + 4];
                a[mt][3] = Ash[(tr + gid + 8)*AST + ib + tig + 4];
            }
            #pragma unroll
            for (int nt = 0; nt < 2; nt++) {
                uint32_t b0 = Vsh[(h_l*16 + nt*8 + gid)*AST + ib + tig    ];
                uint32_t b1 = Vsh[(h_l*16 + nt*8 + gid)*AST + ib + tig + 4];
                #pragma unroll
                for (int mt = 0; mt < 2; mt++)
                    mma_tf32(c[mt][nt][0], c[mt][nt][1], c[mt][nt][2], c[mt][nt][3],
                             a[mt][0], a[mt][1], a[mt][2], a[mt][3], b0, b1);
            }
        }
        __syncthreads();
    }

    #pragma unroll
    for (int mt = 0; mt < 2; mt++)
        #pragma unroll
        for (int nt = 0; nt < 2; nt++) {
            int t0 = mh*32 + mt*16 + gid;
            int k0 = nt*8 + 2*tig;
            Lsh[h_l][t0    ][k0    ] = c[mt][nt][0];
            Lsh[h_l][t0    ][k0 + 1] = c[mt][nt][1];
            Lsh[h_l][t0 + 8][k0    ] = c[mt][nt][2];
            Lsh[h_l][t0 + 8][k0 + 1] = c[mt][nt][3];
        }
    __syncthreads();

    int hh = tid >> 6, t = tid & 63;
    float m = -1e30f;
    #pragma unroll
    for (int k = 0; k < An; k++) m = fmaxf(m, Lsh[hh][t][k]);
    float e[An]; float ssum = 0.f;
    #pragma unroll
    for (int k = 0; k < An; k++) { e[k] = expf(Lsh[hh][t][k] - m); ssum += e[k]; }
    float w = g_taupdf[hq*HB + hh] / ssum;
    #pragma unroll
    for (int k = 0; k < An; k++)
        atomicAdd(&out_pi[((size_t)t*Bn + n)*An + k], e[k] * w);
}

// ---------------- launch ----------------
extern "C" void kernel_launch(void* const* d_in, const int* in_sizes, int n_in,
                              void* d_out, int out_size) {
    const float* logp_o = (const float*)d_in[0];
    const float* logp_u = (const float*)d_in[1];
    const float* value  = (const float*)d_in[2];
    const float* b      = (const float*)d_in[3];
    const float* u      = (const float*)d_in[4];
    const float* v      = (const float*)d_in[5];
    const float* tau    = (const float*)d_in[6];

    float* out    = (float*)d_out;
    float* out_b  = out;                       // [T,B,S]
    float* out_pi = out + (size_t)Tn*Bn*Sn;    // [T,B,A]

    static int smem_set = 0;
    if (!smem_set) {
        cudaFuncSetAttribute(k_scan, cudaFuncAttributeMaxDynamicSharedMemorySize, SMEM_TOT);
        smem_set = 1;
    }

    k_pv<<<An, 64>>>(u, v);
    k_gram<<<Sn, 128>>>(u);
    k_trans16<<<dim3(Sn/16, An), 512>>>();
    k_taupdf<<<1, 32>>>(tau);
    k_alpha_a<<<(Tn*Bn + 127)/128, 128>>>(logp_u);
    k_po<<<(Tn*Bn*Sn)/512, 512>>>(logp_o);     // also zeroes g_normP
    k_init_bel<<<Bn, Sn>>>(b);                 // writes buf0 + t=0 norm seed

    k_scan<<<NUNITS, 256, SMEM_TOT>>>(out_b);

    k_fix<<<Tn*Bn, Sn>>>(out_b);
    cudaMemsetAsync(out_pi, 0, sizeof(float)*(size_t)Tn*Bn*An);
    k_plan<<<dim3(Bn, Hn/HB), 256>>>(value, out_b, out_pi);
}

// round 14
// speedup vs baseline: 1.4076x; 1.4076x over previous
#include <cuda_runtime.h>
#include <cuda_fp16.h>
#include <math.h>
#include <stdint.h>

#define Tn 64
#define Bn 64
#define Sn 512
#define An 16
#define Rn 64
#define Hn 32
#define EPSF 1e-6f
#define BSCALE 4096.f

#define NUNITS 128       // persistent CTAs: one per 4-j chunk (all 16 k local)

// dynamic smem layout (bytes)
#define TSL_B    65536           // T slab: [32 ib][8 col8][32 lane][2 reg] fp16 = 64 KB
#define CSH_ROW4 65              // uint4 per belief row (512 halves + 8 pad)
#define CSH_B    (64*CSH_ROW4*16)    // 66560
#define AWSH_F   (64*17)
#define SMEM_TOT (TSL_B + CSH_B + AWSH_F*4 + 256*4 + 64*4)   // 137728

// ---------------- scratch (device globals; no allocation) ----------------
// T permuted: [jc(128)][ib(32)][col8(8)][lane(32)][reg(2)] halves, col = k*4 + (j&3)
__device__ __align__(16) unsigned short g_transPh[(size_t)An*Sn*Sn];  // 8.4 MB
__device__ float g_G[Sn*Sn];
__device__ float g_p[An*Sn];
__device__ float g_taupdf[Hn];
__device__ float g_alpha_a[(size_t)Tn*Bn*An];
__device__ __align__(16) __half g_belN[2*Bn*Sn];              // double-buffered belief [n][i], scaled x4096
__device__ __align__(16) float g_po[(size_t)Tn*Bn*Sn];        // exp(logp_o), 8 MB
__device__ __align__(16) float g_normP[(Tn+1)*Bn*8];          // per (t+1, n, slot) norm partials

// hierarchical barrier: 8 spread group counters + root + single broadcast gen
__device__ __align__(128) int g_bar_cnt[8*32];   // stride-32 ints = 128 B apart
__device__ int          g_bar_root;
__device__ volatile int g_bar_gen;

// ---------------- helpers ----------------
__device__ __forceinline__ uint32_t f2tf32(float x) {
    uint32_t u;
    asm("cvt.rna.tf32.f32 %0, %1;" : "=r"(u) : "f"(x));
    return u;
}

__device__ __forceinline__ void red_add(float* p, float v) {
    asm volatile("red.global.add.f32 [%0], %1;" :: "l"(p), "f"(v) : "memory");
}

__device__ __forceinline__ void mma_f16(float& c0, float& c1, float& c2, float& c3,
                                        uint32_t a0, uint32_t a1, uint32_t a2, uint32_t a3,
                                        uint32_t b0, uint32_t b1) {
    asm volatile("mma.sync.aligned.m16n8k16.row.col.f32.f16.f16.f32 "
                 "{%0,%1,%2,%3},{%4,%5,%6,%7},{%8,%9},{%0,%1,%2,%3};\n"
                 : "+f"(c0), "+f"(c1), "+f"(c2), "+f"(c3)
                 : "r"(a0), "r"(a1), "r"(a2), "r"(a3), "r"(b0), "r"(b1));
}

__device__ __forceinline__ void mma_tf32(float& c0, float& c1, float& c2, float& c3,
                                         uint32_t a0, uint32_t a1, uint32_t a2, uint32_t a3,
                                         uint32_t b0, uint32_t b1) {
    asm volatile("mma.sync.aligned.m16n8k8.row.col.f32.tf32.tf32.f32 "
                 "{%0,%1,%2,%3},{%4,%5,%6,%7},{%8,%9},{%0,%1,%2,%3};\n"
                 : "+f"(c0), "+f"(c1), "+f"(c2), "+f"(c3)
                 : "r"(a0), "r"(a1), "r"(a2), "r"(a3), "r"(b0), "r"(b1));
}

// ---------------- precompute: v_norm and p[k][i] = u[i].v_hat[k] ----------------
__global__ void k_pv(const float* __restrict__ u, const float* __restrict__ v) {
    int k = blockIdx.x;
    int t = threadIdx.x;  // 64
    __shared__ float vn[Rn];
    __shared__ float sb[64];
    float x = v[k*Rn + t];
    sb[t] = x * x;
    __syncthreads();
    for (int s = 32; s > 0; s >>= 1) { if (t < s) sb[t] += sb[t+s]; __syncthreads(); }
    vn[t] = x * rsqrtf(sb[0]);
    __syncthreads();
    for (int i = t; i < Sn; i += 64) {
        float s = 0.f;
        #pragma unroll
        for (int r = 0; r < Rn; r++) s += u[i*Rn + r] * vn[r];
        g_p[k*Sn + i] = s;
    }
}

// ---------------- precompute: G[i][j] = u[i].u[j] ----------------
__global__ void k_gram(const float* __restrict__ u) {
    int i = blockIdx.x;
    int tid = threadIdx.x;  // 128
    __shared__ float ui[Rn];
    if (tid < Rn) ui[tid] = u[i*Rn + tid];
    __syncthreads();
    for (int j = tid; j < Sn; j += 128) {
        float s = 0.f;
        #pragma unroll
        for (int r = 0; r < Rn; r++) s += u[j*Rn + r] * ui[r];
        g_G[i*Sn + j] = s;
    }
}

// ---------------- precompute: transition softmax -> j-chunk-sliced fp16 fragment layout ----------------
// block (ib, k): 16 warps, one per row r; each lane owns 16 j-values (j = lane + 32q).
__global__ void __launch_bounds__(512) k_trans16() {
    int ib = blockIdx.x, k = blockIdx.y;   // ib 0..31, k 0..15
    int tid = threadIdx.x;                 // 512
    int r = tid >> 5;                      // warp = row 0..15
    int lane = tid & 31;
    __shared__ __align__(16) unsigned short stage[8192];

    int i = ib*16 + r;
    float pki2 = 2.f * g_p[k*Sn + i];
    const float* Grow = &g_G[i*Sn];
    const float* prow = &g_p[k*Sn];

    float w[16];
    float m = -1e30f;
    #pragma unroll
    for (int q = 0; q < 16; q++) {
        int j = lane + 32*q;
        w[q] = Grow[j] - pki2 * prow[j];
        m = fmaxf(m, w[q]);
    }
    #pragma unroll
    for (int o = 16; o > 0; o >>= 1) m = fmaxf(m, __shfl_xor_sync(0xffffffffu, m, o));
    float s = 0.f;
    #pragma unroll
    for (int q = 0; q < 16; q++) { w[q] = expf(w[q] - m); s += w[q]; }
    #pragma unroll
    for (int o = 16; o > 0; o >>= 1) s += __shfl_xor_sync(0xffffffffu, s, o);
    float inv = 1.f / s;
    int rbits = ((r & 7) >> 1)*4 + (r >> 3)*2 + (r & 1);
    #pragma unroll
    for (int q = 0; q < 16; q++) {
        int j = lane + 32*q;
        stage[(j >> 2)*64 + (j & 3)*16 + rbits] =
            __half_as_ushort(__float2half_rn(w[q] * inv));
    }
    __syncthreads();

    // coalesced writeout: 1024 uint4
    const uint4* s4 = reinterpret_cast<const uint4*>(stage);
    uint4* d4 = reinterpret_cast<uint4*>(g_transPh);
    #pragma unroll
    for (int q = 0; q < 2; q++) {
        int f = tid + q*512;               // 0..1023
        int jc2 = f >> 3, o = f & 7;
        size_t idx4 = ((size_t)(jc2*32 + ib)*8 + (k >> 1))*16 + (k & 1)*8 + o;
        d4[idx4] = s4[f];
    }
}

// ---------------- precompute: normalized Poisson pdf over horizon ----------------
__global__ void k_taupdf(const float* __restrict__ tau) {
    int t = threadIdx.x;  // 32
    float rate = log1pf(expf(tau[0]));
    float kk = (float)(t + 1);
    float lp = kk * logf(rate) - rate - lgammaf(kk + 1.f);
    float p = expf(lp);
    float s = p;
    #pragma unroll
    for (int o = 16; o > 0; o >>= 1) s += __shfl_xor_sync(0xffffffffu, s, o);
    g_taupdf[t] = p / s;
}

// ---------------- precompute: alpha_a = softmax(logp_u) over A ----------------
__global__ void k_alpha_a(const float* __restrict__ logp_u) {
    int idx = blockIdx.x * blockDim.x + threadIdx.x;
    if (idx >= Tn*Bn) return;
    const float* r = logp_u + (size_t)idx*An;
    float m = -1e30f;
    #pragma unroll
    for (int k = 0; k < An; k++) m = fmaxf(m, r[k]);
    float e[An]; float s = 0.f;
    #pragma unroll
    for (int k = 0; k < An; k++) { e[k] = expf(r[k] - m); s += e[k]; }
    float inv = 1.f / s;
    #pragma unroll
    for (int k = 0; k < An; k++) g_alpha_a[(size_t)idx*An + k] = e[k] * inv;
}

// ---------------- precompute: po = exp(logp_o); also zero the norm partials ----------------
__global__ void k_po(const float* __restrict__ logp_o) {
    size_t idx = (size_t)blockIdx.x * 512 + threadIdx.x;
    g_po[idx] = expf(logp_o[idx]);
    if (idx < (size_t)(Tn+1)*Bn*8) g_normP[idx] = 0.f;
}

// ---------------- init belief: fp16 rows [n][i], scaled; seed norm for t=0 ----------------
__global__ void k_init_bel(const float* __restrict__ b) {
    int n = blockIdx.x, j = threadIdx.x;  // (Bn, Sn)
    __shared__ float red[512];
    float bv = b[n*Sn + j] * BSCALE;
    g_belN[n*Sn + j] = __float2half_rn(bv);
    red[j] = bv; __syncthreads();
    for (int s = 256; s > 0; s >>= 1) { if (j < s) red[j] += red[j+s]; __syncthreads(); }
    if (j == 0) g_normP[n*8] = red[0];    // t=0 reads slot sums at index 0
}

// ---------------- grid barrier: 2-level atomic arrive tree + broadcast gen release ----------------
__device__ __forceinline__ void grid_sync_dev(int jc) {
    __syncthreads();
    if (threadIdx.x == 0) {
        int old = g_bar_gen;               // read BEFORE arrive (all CTAs agree)
        __threadfence();                   // release: step outputs visible before arrival
        int g = jc & 7;
        int t = atomicAdd(&g_bar_cnt[g*32], 1);
        if (t == (NUNITS/8) - 1) {         // last in group -> arrive at root
            int r = atomicAdd(&g_bar_root, 1);
            if (r == 7) {                  // last group -> reset + release
                #pragma unroll
                for (int q = 0; q < 8; q++) g_bar_cnt[q*32] = 0;
                g_bar_root = 0;
                __threadfence();
                g_bar_gen = old + 1;
            } else {
                while (g_bar_gen == old) __nanosleep(64);
            }
        } else {
            while (g_bar_gen == old) __nanosleep(64);
        }
    }
    __syncthreads();
    __threadfence();                       // acquire side
}

// ---------------- fused persistent scan: per-CTA j-chunk, all-k local, ONE barrier/step ----------------
__global__ void __launch_bounds__(256, 1)
k_scan(float* __restrict__ out_b) {
    extern __shared__ char smem[];
    uint4*          Tsl4 = reinterpret_cast<uint4*>(smem);
    const uint2*    Tsl2 = reinterpret_cast<const uint2*>(smem);
    char*           cshB = smem + TSL_B;
    uint4*          csh4 = reinterpret_cast<uint4*>(cshB);
    const uint32_t* csh2 = reinterpret_cast<const uint32_t*>(cshB);
    float* awsh  = reinterpret_cast<float*>(cshB + CSH_B);   // [64][17] raw alpha
    float* sacc  = awsh + AWSH_F;                            // [64][4]
    float* invsh = sacc + 256;                               // [64]

    int tid  = threadIdx.x;            // 256
    int jc   = blockIdx.x;             // 0..127 : j-chunk of 4
    int lane = tid & 31;
    int warp = tid >> 5;
    int gid  = lane >> 2;
    int tig  = lane & 3;
    int mw   = warp & 1;               // 2 warps over M (n)
    int nw   = warp >> 1;              // 4 warps over N (cols)
    int nwb  = mw * 32;
    int fn   = tid >> 2;               // final-phase n
    int fj   = tid & 3;                // final-phase jj
    int jj0  = (2*tig) & 3;

    // one-time: load this CTA's T slab (64 KB, contiguous)
    {
        const uint4* srcT = reinterpret_cast<const uint4*>(g_transPh) + (size_t)jc*4096;
        #pragma unroll
        for (int q = 0; q < 16; q++) Tsl4[tid + q*256] = srcT[tid + q*256];
    }
    __syncthreads();

    for (int t = 0; t < Tn; t++) {
        // prefetch po (off critical path), zero sacc, stage alpha + inv + belief
        float pof = __ldg(&g_po[((size_t)t*Bn + fn)*Sn + jc*4 + fj]);
        sacc[tid] = 0.f;
        #pragma unroll
        for (int q = 0; q < 4; q++) {
            int e = tid + q*256;                         // 0..1023
            awsh[(e >> 4)*17 + (e & 15)] =
                __ldg(&g_alpha_a[((size_t)t*Bn + (e >> 4))*An + (e & 15)]);
        }
        if (tid < Bn) {
            const float4* np = reinterpret_cast<const float4*>(&g_normP[(size_t)t*Bn*8 + tid*8]);
            float4 x = __ldcg(np), y = __ldcg(np + 1);
            invsh[tid] = 1.f / (x.x + x.y + x.z + x.w + y.x + y.y + y.z + y.w);
        }
        {
            const uint4* belc = reinterpret_cast<const uint4*>(g_belN + (size_t)(t & 1)*Bn*Sn);
            #pragma unroll
            for (int q = 0; q < 16; q++) {
                int f = tid + q*256;                     // 0..4095
                csh4[(f >> 6)*CSH_ROW4 + (f & 63)] = __ldcg(&belc[f]);
            }
        }
        __syncthreads();

        // GEMM: M[n, col] = sum_i bel[n,i] * T[i, col], col = k*4+jj (64 cols)
        float c[2][2][4];
        #pragma unroll
        for (int mt = 0; mt < 2; mt++)
            #pragma unroll
            for (int nt = 0; nt < 2; nt++)
                #pragma unroll
                for (int r = 0; r < 4; r++) c[mt][nt][r] = 0.f;

        #pragma unroll 8
        for (int ks = 0; ks < 32; ks++) {
            uint32_t a[2][4];
            #pragma unroll
            for (int mt = 0; mt < 2; mt++) {
                int rb = (nwb + mt*16 + gid)*260 + ks*8 + tig;
                a[mt][0] = csh2[rb];
                a[mt][1] = csh2[rb + 8*260];
                a[mt][2] = csh2[rb + 4];
                a[mt][3] = csh2[rb + 8*260 + 4];
            }
            #pragma unroll
            for (int nt = 0; nt < 2; nt++) {
                uint2 bf = Tsl2[(ks*8 + nw*2 + nt)*32 + lane];
                #pragma unroll
                for (int mt = 0; mt < 2; mt++)
                    mma_f16(c[mt][nt][0], c[mt][nt][1], c[mt][nt][2], c[mt][nt][3],
                            a[mt][0], a[mt][1], a[mt][2], a[mt][3], bf.x, bf.y);
            }
        }

        // epilogue: local k-sum with raw alpha weights -> SMEM atomics
        #pragma unroll
        for (int mt = 0; mt < 2; mt++) {
            int n_a = nwb + mt*16 + gid;
            float pa0 = 0.f, pa1 = 0.f, pb0 = 0.f, pb1 = 0.f;
            #pragma unroll
            for (int nt = 0; nt < 2; nt++) {
                int k = nw*4 + nt*2 + (tig >> 1);
                float wA = awsh[n_a*17 + k];
                float wB = awsh[(n_a + 8)*17 + k];
                pa0 += wA * c[mt][nt][0]; pa1 += wA * c[mt][nt][1];
                pb0 += wB * c[mt][nt][2]; pb1 += wB * c[mt][nt][3];
            }
            atomicAdd(&sacc[n_a*4 + jj0],           pa0);
            atomicAdd(&sacc[n_a*4 + jj0 + 1],       pa1);
            atomicAdd(&sacc[(n_a + 8)*4 + jj0],     pb0);
            atomicAdd(&sacc[(n_a + 8)*4 + jj0 + 1], pb1);
        }
        __syncthreads();

        // finalize: val = (s_norm + eps)*po ; write belief (x4096 fp16), out_b, norm REDs
        {
            float val = (sacc[tid] * invsh[fn] + EPSF) * pof;
            float vs  = val * BSCALE;
            out_b[((size_t)t*Bn + fn)*Sn + jc*4 + fj] = vs;   // unnormalized; fixed post-scan
            unsigned short us = __half_as_ushort(__float2half_rn(vs));
            unsigned short* bp = reinterpret_cast<unsigned short*>(
                g_belN + (size_t)((t + 1) & 1)*Bn*Sn) + fn*Sn + jc*4 + fj;
            asm volatile("st.global.cg.u16 [%0], %1;" :: "l"(bp), "h"(us) : "memory");
            float w = vs;
            w += __shfl_xor_sync(0xffffffffu, w, 1);
            w += __shfl_xor_sync(0xffffffffu, w, 2);
            if ((lane & 3) == 0)
                red_add(&g_normP[(size_t)(t + 1)*Bn*8 + fn*8 + (jc & 7)], w);
        }

        grid_sync_dev(jc);
    }
}

// ---------------- post-scan: normalize out_b by per-(t,n) norms ----------------
__global__ void k_fix(float* __restrict__ out_b) {
    int tn = blockIdx.x;            // t*64 + n
    int t = tn >> 6, n = tn & 63;
    __shared__ float inv;
    if (threadIdx.x == 0) {
        const float* np = &g_normP[(size_t)(t + 1)*Bn*8 + n*8];
        float s = np[0] + np[1] + np[2] + np[3] + np[4] + np[5] + np[6] + np[7];
        inv = 1.f / s;
    }
    __syncthreads();
    out_b[(size_t)tn*Sn + threadIdx.x] *= inv;
}

// ---------------- post-scan plan: tf32 MMA logits, softmax over A, tau-weighted sum ----------------
#define HB 4
#define AST 36
__global__ void __launch_bounds__(256)
k_plan(const float* __restrict__ value,
       const float* __restrict__ alpha_b,
       float* __restrict__ out_pi) {
    int n  = blockIdx.x;
    int hq = blockIdx.y;
    int tid = threadIdx.x;
    int lane = tid & 31;
    int warp = tid >> 5;
    int h_l = warp & 3;
    int mh  = warp >> 2;
    int gid = lane >> 2;
    int tig = lane & 3;

    __shared__ uint32_t Ash[64*AST];
    __shared__ uint32_t Vsh[HB*16*AST];
    __shared__ float    Lsh[HB][64][17];

    float c[2][2][4];
    #pragma unroll
    for (int mt = 0; mt < 2; mt++)
        #pragma unroll
        for (int nt = 0; nt < 2; nt++)
            #pragma unroll
            for (int r = 0; r < 4; r++) c[mt][nt][r] = 0.f;

    for (int i0 = 0; i0 < Sn; i0 += 32) {
        #pragma unroll
        for (int q = 0; q < 8; q++) {
            int e = tid + q*256; int ii = e & 31, tt = e >> 5;
            Ash[tt*AST + ii] = f2tf32(alpha_b[((size_t)tt*Bn + n)*Sn + i0 + ii]);
        }
        #pragma unroll
        for (int q = 0; q < 8; q++) {
            int e = tid + q*256; int ii = e & 31, rest = e >> 5;
            int kk2 = rest & 15, hh = rest >> 4;
            Vsh[(hh*16 + kk2)*AST + ii] =
                f2tf32(value[(((size_t)(hq*HB + hh)*Bn + n)*An + kk2)*Sn + i0 + ii]);
        }
        __syncthreads();
        #pragma unroll
        for (int ksl = 0; ksl < 4; ksl++) {
            int ib = ksl*8;
            uint32_t a[2][4];
            #pragma unroll
            for (int mt = 0; mt < 2; mt++) {
                int tr = mh*32 + mt*16;
                a[mt][0] = Ash[(tr + gid    )*AST + ib + tig    ];
                a[mt][1] = Ash[(tr + gid + 8)*AST + ib + tig    ];
                a[mt][2] = Ash[(tr + gid    )*AST + ib + tig + 4];
                a[mt][3] = Ash[(tr + gid + 8)*AST + ib + tig + 4];
            }
            #pragma unroll
            for (int nt = 0; nt < 2; nt++) {
                uint32_t b0 = Vsh[(h_l*16 + nt*8 + gid)*AST + ib + tig    ];
                uint32_t b1 = Vsh[(h_l*16 + nt*8 + gid)*AST + ib + tig + 4];
                #pragma unroll
                for (int mt = 0; mt < 2; mt++)
                    mma_tf32(c[mt][nt][0], c[mt][nt][1], c[mt][nt][2], c[mt][nt][3],
                             a[mt][0], a[mt][1], a[mt][2], a[mt][3], b0, b1);
            }
        }
        __syncthreads();
    }

    #pragma unroll
    for (int mt = 0; mt < 2; mt++)
        #pragma unroll
        for (int nt = 0; nt < 2; nt++) {
            int t0 = mh*32 + mt*16 + gid;
            int k0 = nt*8 + 2*tig;
            Lsh[h_l][t0    ][k0    ] = c[mt][nt][0];
            Lsh[h_l][t0    ][k0 + 1] = c[mt][nt][1];
            Lsh[h_l][t0 + 8][k0    ] = c[mt][nt][2];
            Lsh[h_l][t0 + 8][k0 + 1] = c[mt][nt][3];
        }
    __syncthreads();

    int hh = tid >> 6, t = tid & 63;
    float m = -1e30f;
    #pragma unroll
    for (int k = 0; k < An; k++) m = fmaxf(m, Lsh[hh][t][k]);
    float e[An]; float ssum = 0.f;
    #pragma unroll
    for (int k = 0; k < An; k++) { e[k] = expf(Lsh[hh][t][k] - m); ssum += e[k]; }
    float w = g_taupdf[hq*HB + hh] / ssum;
    #pragma unroll
    for (int k = 0; k < An; k++)
        atomicAdd(&out_pi[((size_t)t*Bn + n)*An + k], e[k] * w);
}

// ---------------- launch ----------------
extern "C" void kernel_launch(void* const* d_in, const int* in_sizes, int n_in,
                              void* d_out, int out_size) {
    const float* logp_o = (const float*)d_in[0];
    const float* logp_u = (const float*)d_in[1];
    const float* value  = (const float*)d_in[2];
    const float* b      = (const float*)d_in[3];
    const float* u      = (const float*)d_in[4];
    const float* v      = (const float*)d_in[5];
    const float* tau    = (const float*)d_in[6];

    float* out    = (float*)d_out;
    float* out_b  = out;                       // [T,B,S]
    float* out_pi = out + (size_t)Tn*Bn*Sn;    // [T,B,A]

    static int smem_set = 0;
    if (!smem_set) {
        cudaFuncSetAttribute(k_scan, cudaFuncAttributeMaxDynamicSharedMemorySize, SMEM_TOT);
        smem_set = 1;
    }

    k_pv<<<An, 64>>>(u, v);
    k_gram<<<Sn, 128>>>(u);
    k_trans16<<<dim3(Sn/16, An), 512>>>();
    k_taupdf<<<1, 32>>>(tau);
    k_alpha_a<<<(Tn*Bn + 127)/128, 128>>>(logp_u);
    k_po<<<(Tn*Bn*Sn)/512, 512>>>(logp_o);     // also zeroes g_normP
    k_init_bel<<<Bn, Sn>>>(b);                 // writes buf0 + t=0 norm seed

    k_scan<<<NUNITS, 256, SMEM_TOT>>>(out_b);

    k_fix<<<Tn*Bn, Sn>>>(out_b);
    cudaMemsetAsync(out_pi, 0, sizeof(float)*(size_t)Tn*Bn*An);
    k_plan<<<dim3(Bn, Hn/HB), 256>>>(value, out_b, out_pi);
}

// round 15
// speedup vs baseline: 1.4984x; 1.0645x over previous
#include <cuda_runtime.h>
#include <cuda_fp16.h>
#include <math.h>
#include <stdint.h>

#define Tn 64
#define Bn 64
#define Sn 512
#define An 16
#define Rn 64
#define Hn 32
#define EPSF 1e-6f
#define BSCALE 4096.f

#define NUNITS 128       // persistent CTAs: one per 4-j chunk (all 16 k local)

// scan dynamic smem layout (bytes)
#define TSL_B    65536           // T slab: [32 ib][8 col8][32 lane][2 reg] fp16 = 64 KB
#define CSH_ROW4 65              // uint4 per belief row (512 halves + 8 pad)
#define CSH_B    (64*CSH_ROW4*16)    // 66560
#define AWSH_F   (64*17)
#define SMEM_TOT (TSL_B + CSH_B + AWSH_F*4 + 256*4 + 64*4)   // 137728

// plan dynamic smem layout (floats)
#define PAST 516                 // alpha tile stride (516 % 32 == 4 -> bank-safe frag loads)
#define PVST 68                  // value tile stride (68 % 32 == 4)
#define PLAN_F (32*PAST + 8*16*PVST + 8*32*17 + 32*17 + 32)  // 30144 floats
#define PLAN_B (PLAN_F*4)                                     // 120576 bytes

// ---------------- scratch (device globals; no allocation) ----------------
// T permuted: [jc(128)][ib(32)][col8(8)][lane(32)][reg(2)] halves, col = k*4 + (j&3)
__device__ __align__(16) unsigned short g_transPh[(size_t)An*Sn*Sn];  // 8.4 MB
__device__ float g_G[Sn*Sn];
__device__ float g_p[An*Sn];
__device__ float g_taupdf[Hn];
__device__ float g_alpha_a[(size_t)Tn*Bn*An];
__device__ __align__(16) __half g_belN[2*Bn*Sn];              // double-buffered belief [n][i], scaled x4096
__device__ __align__(16) float g_po[(size_t)Tn*Bn*Sn];        // exp(logp_o), 8 MB
__device__ __align__(16) float g_normP[(Tn+1)*Bn*8];          // per (t+1, n, slot) norm partials

// hierarchical barrier: 8 spread group counters + root + single broadcast gen
__device__ __align__(128) int g_bar_cnt[8*32];   // stride-32 ints = 128 B apart
__device__ int          g_bar_root;
__device__ volatile int g_bar_gen;

// ---------------- helpers ----------------
__device__ __forceinline__ uint32_t f2tf32(float x) {
    uint32_t u;
    asm("cvt.rna.tf32.f32 %0, %1;" : "=r"(u) : "f"(x));
    return u;
}

__device__ __forceinline__ void red_add(float* p, float v) {
    asm volatile("red.global.add.f32 [%0], %1;" :: "l"(p), "f"(v) : "memory");
}

__device__ __forceinline__ void mma_f16(float& c0, float& c1, float& c2, float& c3,
                                        uint32_t a0, uint32_t a1, uint32_t a2, uint32_t a3,
                                        uint32_t b0, uint32_t b1) {
    asm volatile("mma.sync.aligned.m16n8k16.row.col.f32.f16.f16.f32 "
                 "{%0,%1,%2,%3},{%4,%5,%6,%7},{%8,%9},{%0,%1,%2,%3};\n"
                 : "+f"(c0), "+f"(c1), "+f"(c2), "+f"(c3)
                 : "r"(a0), "r"(a1), "r"(a2), "r"(a3), "r"(b0), "r"(b1));
}

__device__ __forceinline__ void mma_tf32(float& c0, float& c1, float& c2, float& c3,
                                         uint32_t a0, uint32_t a1, uint32_t a2, uint32_t a3,
                                         uint32_t b0, uint32_t b1) {
    asm volatile("mma.sync.aligned.m16n8k8.row.col.f32.tf32.tf32.f32 "
                 "{%0,%1,%2,%3},{%4,%5,%6,%7},{%8,%9},{%0,%1,%2,%3};\n"
                 : "+f"(c0), "+f"(c1), "+f"(c2), "+f"(c3)
                 : "r"(a0), "r"(a1), "r"(a2), "r"(a3), "r"(b0), "r"(b1));
}

// ---------------- fused precompute 1: pv (blocks 0..15) + gram (blocks 16..527) ----------------
__global__ void __launch_bounds__(128) k_pre1(const float* __restrict__ u, const float* __restrict__ v) {
    int bid = blockIdx.x;
    int tid = threadIdx.x;  // 128
    if (bid < An) {
        // pv: p[k][i] = u[i] . v_hat[k]
        int k = bid;
        __shared__ float vn[Rn];
        __shared__ float sb[Rn];
        float x = 0.f;
        if (tid < Rn) { x = v[k*Rn + tid]; sb[tid] = x * x; }
        __syncthreads();
        for (int s = 32; s > 0; s >>= 1) { if (tid < s) sb[tid] += sb[tid+s]; __syncthreads(); }
        if (tid < Rn) vn[tid] = x * rsqrtf(sb[0]);
        __syncthreads();
        for (int i = tid; i < Sn; i += 128) {
            float s = 0.f;
            #pragma unroll
            for (int r = 0; r < Rn; r++) s += u[i*Rn + r] * vn[r];
            g_p[k*Sn + i] = s;
        }
    } else {
        // gram: G[i][j] = u[i] . u[j]
        int i = bid - An;
        __shared__ float ui[Rn];
        if (tid < Rn) ui[tid] = u[i*Rn + tid];
        __syncthreads();
        for (int j = tid; j < Sn; j += 128) {
            float s = 0.f;
            #pragma unroll
            for (int r = 0; r < Rn; r++) s += u[j*Rn + r] * ui[r];
            g_G[i*Sn + j] = s;
        }
    }
}

// ---------------- precompute: transition softmax -> j-chunk-sliced fp16 fragment layout ----------------
__global__ void __launch_bounds__(512) k_trans16() {
    int ib = blockIdx.x, k = blockIdx.y;   // ib 0..31, k 0..15
    int tid = threadIdx.x;                 // 512
    int r = tid >> 5;                      // warp = row 0..15
    int lane = tid & 31;
    __shared__ __align__(16) unsigned short stage[8192];

    int i = ib*16 + r;
    float pki2 = 2.f * g_p[k*Sn + i];
    const float* Grow = &g_G[i*Sn];
    const float* prow = &g_p[k*Sn];

    float w[16];
    float m = -1e30f;
    #pragma unroll
    for (int q = 0; q < 16; q++) {
        int j = lane + 32*q;
        w[q] = Grow[j] - pki2 * prow[j];
        m = fmaxf(m, w[q]);
    }
    #pragma unroll
    for (int o = 16; o > 0; o >>= 1) m = fmaxf(m, __shfl_xor_sync(0xffffffffu, m, o));
    float s = 0.f;
    #pragma unroll
    for (int q = 0; q < 16; q++) { w[q] = expf(w[q] - m); s += w[q]; }
    #pragma unroll
    for (int o = 16; o > 0; o >>= 1) s += __shfl_xor_sync(0xffffffffu, s, o);
    float inv = 1.f / s;
    int rbits = ((r & 7) >> 1)*4 + (r >> 3)*2 + (r & 1);
    #pragma unroll
    for (int q = 0; q < 16; q++) {
        int j = lane + 32*q;
        stage[(j >> 2)*64 + (j & 3)*16 + rbits] =
            __half_as_ushort(__float2half_rn(w[q] * inv));
    }
    __syncthreads();

    const uint4* s4 = reinterpret_cast<const uint4*>(stage);
    uint4* d4 = reinterpret_cast<uint4*>(g_transPh);
    #pragma unroll
    for (int q = 0; q < 2; q++) {
        int f = tid + q*512;               // 0..1023
        int jc2 = f >> 3, o = f & 7;
        size_t idx4 = ((size_t)(jc2*32 + ib)*8 + (k >> 1))*16 + (k & 1)*8 + o;
        d4[idx4] = s4[f];
    }
}

// ---------------- fused precompute 3: po + normP zero + alpha_a + init_bel + taupdf ----------------
__global__ void __launch_bounds__(512) k_pre3(const float* __restrict__ logp_o,
                                              const float* __restrict__ logp_u,
                                              const float* __restrict__ b,
                                              const float* __restrict__ tau) {
    int bid = blockIdx.x;                  // 4096
    int tid = threadIdx.x;                 // 512
    size_t idx = (size_t)bid*512 + tid;
    g_po[idx] = expf(logp_o[idx]);
    // zero norm partials EXCEPT the t=0 rows (seeded by init_bel blocks below)
    if (idx >= (size_t)Bn*8 && idx < (size_t)(Tn+1)*Bn*8) g_normP[idx] = 0.f;

    if (bid < 8) {
        // alpha_a: one (t,n) row per thread; idx 0..4095
        const float* r = logp_u + idx*An;
        float m = -1e30f;
        #pragma unroll
        for (int k = 0; k < An; k++) m = fmaxf(m, r[k]);
        float e[An]; float s = 0.f;
        #pragma unroll
        for (int k = 0; k < An; k++) { e[k] = expf(r[k] - m); s += e[k]; }
        float inv = 1.f / s;
        #pragma unroll
        for (int k = 0; k < An; k++) g_alpha_a[idx*An + k] = e[k] * inv;
    }

    if (bid >= 64 && bid < 128) {
        // init_bel: n = bid-64, j = tid; writes t=0 norm row (all 8 slots)
        int n = bid - 64, j = tid;
        __shared__ float red[512];
        float bv = b[n*Sn + j] * BSCALE;
        g_belN[n*Sn + j] = __float2half_rn(bv);
        red[j] = bv; __syncthreads();
        for (int s = 256; s > 0; s >>= 1) { if (j < s) red[j] += red[j+s]; __syncthreads(); }
        if (j < 8) g_normP[n*8 + j] = (j == 0) ? red[0] : 0.f;
    }

    if (bid == 4095 && tid < 32) {
        // taupdf (warp-only, no block sync)
        float rate = log1pf(expf(tau[0]));
        float kk = (float)(tid + 1);
        float lp = kk * logf(rate) - rate - lgammaf(kk + 1.f);
        float p = expf(lp);
        float s = p;
        #pragma unroll
        for (int o = 16; o > 0; o >>= 1) s += __shfl_xor_sync(0xffffffffu, s, o);
        g_taupdf[tid] = p / s;
    }
}

// ---------------- grid barrier: 2-level atomic arrive tree + broadcast gen release ----------------
__device__ __forceinline__ void grid_sync_dev(int jc) {
    __syncthreads();
    if (threadIdx.x == 0) {
        int old = g_bar_gen;               // read BEFORE arrive (all CTAs agree)
        __threadfence();                   // release: step outputs visible before arrival
        int g = jc & 7;
        int t = atomicAdd(&g_bar_cnt[g*32], 1);
        if (t == (NUNITS/8) - 1) {         // last in group -> arrive at root
            int r = atomicAdd(&g_bar_root, 1);
            if (r == 7) {                  // last group -> reset + release
                #pragma unroll
                for (int q = 0; q < 8; q++) g_bar_cnt[q*32] = 0;
                g_bar_root = 0;
                __threadfence();
                g_bar_gen = old + 1;
            } else {
                while (g_bar_gen == old) __nanosleep(64);
            }
        } else {
            while (g_bar_gen == old) __nanosleep(64);
        }
    }
    __syncthreads();
    __threadfence();                       // acquire side
}

// ---------------- fused persistent scan: per-CTA j-chunk, all-k local, ONE barrier/step ----------------
__global__ void __launch_bounds__(256, 1)
k_scan(float* __restrict__ out_b) {
    extern __shared__ char smem[];
    uint4*          Tsl4 = reinterpret_cast<uint4*>(smem);
    const uint2*    Tsl2 = reinterpret_cast<const uint2*>(smem);
    char*           cshB = smem + TSL_B;
    uint4*          csh4 = reinterpret_cast<uint4*>(cshB);
    const uint32_t* csh2 = reinterpret_cast<const uint32_t*>(cshB);
    float* awsh  = reinterpret_cast<float*>(cshB + CSH_B);   // [64][17] raw alpha
    float* sacc  = awsh + AWSH_F;                            // [64][4]
    float* invsh = sacc + 256;                               // [64]

    int tid  = threadIdx.x;            // 256
    int jc   = blockIdx.x;             // 0..127 : j-chunk of 4
    int lane = tid & 31;
    int warp = tid >> 5;
    int gid  = lane >> 2;
    int tig  = lane & 3;
    int mw   = warp & 1;               // 2 warps over M (n)
    int nw   = warp >> 1;              // 4 warps over N (cols)
    int nwb  = mw * 32;
    int fn   = tid >> 2;               // final-phase n
    int fj   = tid & 3;                // final-phase jj
    int jj0  = (2*tig) & 3;

    // one-time: load this CTA's T slab (64 KB, contiguous)
    {
        const uint4* srcT = reinterpret_cast<const uint4*>(g_transPh) + (size_t)jc*4096;
        #pragma unroll
        for (int q = 0; q < 16; q++) Tsl4[tid + q*256] = srcT[tid + q*256];
    }
    __syncthreads();

    for (int t = 0; t < Tn; t++) {
        // prefetch po (off critical path), zero sacc, stage alpha + inv + belief
        float pof = __ldg(&g_po[((size_t)t*Bn + fn)*Sn + jc*4 + fj]);
        sacc[tid] = 0.f;
        #pragma unroll
        for (int q = 0; q < 4; q++) {
            int e = tid + q*256;                         // 0..1023
            awsh[(e >> 4)*17 + (e & 15)] =
                __ldg(&g_alpha_a[((size_t)t*Bn + (e >> 4))*An + (e & 15)]);
        }
        if (tid < Bn) {
            const float4* np = reinterpret_cast<const float4*>(&g_normP[(size_t)t*Bn*8 + tid*8]);
            float4 x = __ldcg(np), y = __ldcg(np + 1);
            invsh[tid] = 1.f / (x.x + x.y + x.z + x.w + y.x + y.y + y.z + y.w);
        }
        {
            const uint4* belc = reinterpret_cast<const uint4*>(g_belN + (size_t)(t & 1)*Bn*Sn);
            #pragma unroll
            for (int q = 0; q < 16; q++) {
                int f = tid + q*256;                     // 0..4095
                csh4[(f >> 6)*CSH_ROW4 + (f & 63)] = __ldcg(&belc[f]);
            }
        }
        __syncthreads();

        // GEMM: M[n, col] = sum_i bel[n,i] * T[i, col], col = k*4+jj (64 cols)
        float c[2][2][4];
        #pragma unroll
        for (int mt = 0; mt < 2; mt++)
            #pragma unroll
            for (int nt = 0; nt < 2; nt++)
                #pragma unroll
                for (int r = 0; r < 4; r++) c[mt][nt][r] = 0.f;

        #pragma unroll 8
        for (int ks = 0; ks < 32; ks++) {
            uint32_t a[2][4];
            #pragma unroll
            for (int mt = 0; mt < 2; mt++) {
                int rb = (nwb + mt*16 + gid)*260 + ks*8 + tig;
                a[mt][0] = csh2[rb];
                a[mt][1] = csh2[rb + 8*260];
                a[mt][2] = csh2[rb + 4];
                a[mt][3] = csh2[rb + 8*260 + 4];
            }
            #pragma unroll
            for (int nt = 0; nt < 2; nt++) {
                uint2 bf = Tsl2[(ks*8 + nw*2 + nt)*32 + lane];
                #pragma unroll
                for (int mt = 0; mt < 2; mt++)
                    mma_f16(c[mt][nt][0], c[mt][nt][1], c[mt][nt][2], c[mt][nt][3],
                            a[mt][0], a[mt][1], a[mt][2], a[mt][3], bf.x, bf.y);
            }
        }

        // epilogue: local k-sum with raw alpha weights -> SMEM atomics
        #pragma unroll
        for (int mt = 0; mt < 2; mt++) {
            int n_a = nwb + mt*16 + gid;
            float pa0 = 0.f, pa1 = 0.f, pb0 = 0.f, pb1 = 0.f;
            #pragma unroll
            for (int nt = 0; nt < 2; nt++) {
                int k = nw*4 + nt*2 + (tig >> 1);
                float wA = awsh[n_a*17 + k];
                float wB = awsh[(n_a + 8)*17 + k];
                pa0 += wA * c[mt][nt][0]; pa1 += wA * c[mt][nt][1];
                pb0 += wB * c[mt][nt][2]; pb1 += wB * c[mt][nt][3];
            }
            atomicAdd(&sacc[n_a*4 + jj0],           pa0);
            atomicAdd(&sacc[n_a*4 + jj0 + 1],       pa1);
            atomicAdd(&sacc[(n_a + 8)*4 + jj0],     pb0);
            atomicAdd(&sacc[(n_a + 8)*4 + jj0 + 1], pb1);
        }
        __syncthreads();

        // finalize: val = (s_norm + eps)*po ; write belief (x4096 fp16), out_b, norm REDs
        {
            float val = (sacc[tid] * invsh[fn] + EPSF) * pof;
            float vs  = val * BSCALE;
            out_b[((size_t)t*Bn + fn)*Sn + jc*4 + fj] = vs;   // unnormalized; fixed in k_plan
            unsigned short us = __half_as_ushort(__float2half_rn(vs));
            unsigned short* bp = reinterpret_cast<unsigned short*>(
                g_belN + (size_t)((t + 1) & 1)*Bn*Sn) + fn*Sn + jc*4 + fj;
            asm volatile("st.global.cg.u16 [%0], %1;" :: "l"(bp), "h"(us) : "memory");
            float w = vs;
            w += __shfl_xor_sync(0xffffffffu, w, 1);
            w += __shfl_xor_sync(0xffffffffu, w, 2);
            if ((lane & 3) == 0)
                red_add(&g_normP[(size_t)(t + 1)*Bn*8 + fn*8 + (jc & 7)], w);
        }

        grid_sync_dev(jc);
    }
}

// ---------------- post-scan plan: per-(n, t-half) block, SMEM-resident alpha, fused normalize ----------------
__global__ void __launch_bounds__(256, 1)
k_plan(const float* __restrict__ value,
       float* __restrict__ out_b,
       float* __restrict__ out_pi) {
    extern __shared__ float ps[];
    uint32_t* AshF = reinterpret_cast<uint32_t*>(ps);            // [32 t][516] tf32
    uint32_t* Vsh  = reinterpret_cast<uint32_t*>(ps + 32*PAST);  // [8h*16k][68] tf32
    float* Lsh  = ps + 32*PAST + 8*16*PVST;                      // [8h][32t][17]
    float* psh  = Lsh + 8*32*17;                                 // [32t][17]
    float* invt = psh + 32*17;                                   // [32]

    int n  = blockIdx.x;
    int tg = blockIdx.y;          // t-half: rows tg*32 .. tg*32+31
    int tid = threadIdx.x;        // 256
    int lane = tid & 31;
    int warp = tid >> 5;          // 0..7 : h within the current hq-group
    int gid = lane >> 2;
    int tig = lane & 3;

    // per-t inverse norms
    if (tid < 32) {
        const float* np = &g_normP[(size_t)(tg*32 + tid + 1)*Bn*8 + n*8];
        invt[tid] = 1.f / (np[0]+np[1]+np[2]+np[3]+np[4]+np[5]+np[6]+np[7]);
    }
    for (int e = tid; e < 32*17; e += 256) psh[e] = 0.f;
    __syncthreads();

    // stage full normalized alpha tile; write normalized out_b back (fused k_fix)
    #pragma unroll 4
    for (int q = 0; q < 64; q++) {
        int e = tid + q*256;                 // 0..16383
        int ii = e & 511, tt = e >> 9;       // tt 0..31
        float* op = &out_b[((size_t)(tg*32 + tt)*Bn + n)*Sn + ii];
        float valn = *op * invt[tt];
        *op = valn;
        AshF[tt*PAST + ii] = f2tf32(valn);
    }
    __syncthreads();

    for (int hq = 0; hq < 4; hq++) {          // 4 groups of 8 h (one per warp)
        float c[2][2][4];
        #pragma unroll
        for (int mt = 0; mt < 2; mt++)
            #pragma unroll
            for (int nt = 0; nt < 2; nt++)
                #pragma unroll
                for (int r = 0; r < 4; r++) c[mt][nt][r] = 0.f;

        for (int ch = 0; ch < 8; ch++) {      // i-chunks of 64
            // stage Vsh: 8h x 16k x 64i
            #pragma unroll
            for (int q = 0; q < 32; q++) {
                int e = tid + q*256;          // 0..8191
                int ii = e & 63, rest = e >> 6;          // rest 0..127
                int kk2 = rest & 15, hh = rest >> 4;     // hh 0..7
                Vsh[(hh*16 + kk2)*PVST + ii] =
                    f2tf32(value[(((size_t)(hq*8 + hh)*Bn + n)*An + kk2)*Sn + ch*64 + ii]);
            }
            __syncthreads();
            #pragma unroll
            for (int ksl = 0; ksl < 8; ksl++) {
                int ib = ksl*8;
                int col = ch*64 + ib;
                uint32_t a[2][4];
                #pragma unroll
                for (int mt = 0; mt < 2; mt++) {
                    int tr = mt*16;
                    a[mt][0] = AshF[(tr + gid    )*PAST + col + tig    ];
                    a[mt][1] = AshF[(tr + gid + 8)*PAST + col + tig    ];
                    a[mt][2] = AshF[(tr + gid    )*PAST + col + tig + 4];
                    a[mt][3] = AshF[(tr + gid + 8)*PAST + col + tig + 4];
                }
                #pragma unroll
                for (int nt = 0; nt < 2; nt++) {
                    uint32_t b0 = Vsh[(warp*16 + nt*8 + gid)*PVST + ib + tig    ];
                    uint32_t b1 = Vsh[(warp*16 + nt*8 + gid)*PVST + ib + tig + 4];
                    #pragma unroll
                    for (int mt = 0; mt < 2; mt++)
                        mma_tf32(c[mt][nt][0], c[mt][nt][1], c[mt][nt][2], c[mt][nt][3],
                                 a[mt][0], a[mt][1], a[mt][2], a[mt][3], b0, b1);
                }
            }
            __syncthreads();
        }

        // scatter logits to Lsh[warp][t][k]
        #pragma unroll
        for (int mt = 0; mt < 2; mt++)
            #pragma unroll
            for (int nt = 0; nt < 2; nt++) {
                int t0 = mt*16 + gid;
                int k0 = nt*8 + 2*tig;
                Lsh[(warp*32 + t0    )*17 + k0    ] = c[mt][nt][0];
                Lsh[(warp*32 + t0    )*17 + k0 + 1] = c[mt][nt][1];
                Lsh[(warp*32 + t0 + 8)*17 + k0    ] = c[mt][nt][2];
                Lsh[(warp*32 + t0 + 8)*17 + k0 + 1] = c[mt][nt][3];
            }
        __syncthreads();

        // softmax per (h,t): 256 threads = 8h x 32t; write weighted pi back into Lsh
        {
            int hh = tid >> 5, t = tid & 31;
            float* Lr = &Lsh[(hh*32 + t)*17];
            float m = -1e30f;
            #pragma unroll
            for (int k = 0; k < An; k++) m = fmaxf(m, Lr[k]);
            float e[An]; float ssum = 0.f;
            #pragma unroll
            for (int k = 0; k < An; k++) { e[k] = expf(Lr[k] - m); ssum += e[k]; }
            float w = g_taupdf[hq*8 + hh] / ssum;
            #pragma unroll
            for (int k = 0; k < An; k++) Lr[k] = e[k] * w;
        }
        __syncthreads();

        // deterministic accumulate into psh: 256 threads = 32t x (8 groups of 2 k)
        {
            int t = tid >> 3, k0 = (tid & 7)*2;
            #pragma unroll
            for (int kq = 0; kq < 2; kq++) {
                int k = k0 + kq;
                float s = 0.f;
                #pragma unroll
                for (int hh = 0; hh < 8; hh++) s += Lsh[(hh*32 + t)*17 + k];
                psh[t*17 + k] += s;
            }
        }
        __syncthreads();
    }

    // store out_pi directly (no atomics, no memset)
    #pragma unroll
    for (int q = 0; q < 2; q++) {
        int e = tid + q*256;                 // 0..511
        int t = e >> 4, k = e & 15;
        out_pi[((size_t)(tg*32 + t)*Bn + n)*An + k] = psh[t*17 + k];
    }
}

// ---------------- launch ----------------
extern "C" void kernel_launch(void* const* d_in, const int* in_sizes, int n_in,
                              void* d_out, int out_size) {
    const float* logp_o = (const float*)d_in[0];
    const float* logp_u = (const float*)d_in[1];
    const float* value  = (const float*)d_in[2];
    const float* b      = (const float*)d_in[3];
    const float* u      = (const float*)d_in[4];
    const float* v      = (const float*)d_in[5];
    const float* tau    = (const float*)d_in[6];

    float* out    = (float*)d_out;
    float* out_b  = out;                       // [T,B,S]
    float* out_pi = out + (size_t)Tn*Bn*Sn;    // [T,B,A]

    static int smem_set = 0;
    if (!smem_set) {
        cudaFuncSetAttribute(k_scan, cudaFuncAttributeMaxDynamicSharedMemorySize, SMEM_TOT);
        cudaFuncSetAttribute(k_plan, cudaFuncAttributeMaxDynamicSharedMemorySize, PLAN_B);
        smem_set = 1;
    }

    k_pre1<<<An + Sn, 128>>>(u, v);                         // launch 0
    k_trans16<<<dim3(Sn/16, An), 512>>>();                  // launch 1
    k_pre3<<<4096, 512>>>(logp_o, logp_u, b, tau);          // launch 2
    k_scan<<<NUNITS, 256, SMEM_TOT>>>(out_b);               // launch 3  <- ncu target
    k_plan<<<dim3(Bn, 2), 256, PLAN_B>>>(value, out_b, out_pi);  // launch 4
}